// round 5
// baseline (speedup 1.0000x reference)
#include <cuda_runtime.h>

// FocalBCELoss: mean over [N,C] of -( t*log(p)*(1-p)^2*alpha[c] + (1-t)*log(1-p)*p^2 )
// t in {0,1} exactly -> single-log formulation:
//   x = t?p:(1-p); q = 1-x; a = (t? alpha[c] : 1) * ln2
//   loss_elem = -log2(x) * q*q * a
// Accumulate sum of log2(x)*q*q*a, output -sum/(N*C).

#define LN2F 0.69314718055994530942f

__device__ double g_sum;

// ---- packed f32x2 helpers (sm_100+ packed fp32 pipe; ptxas won't auto-fuse) ----
static __device__ __forceinline__ unsigned long long pk2(float lo, float hi) {
    unsigned long long r;
    asm("mov.b64 %0, {%1, %2};" : "=l"(r) : "f"(lo), "f"(hi));
    return r;
}
static __device__ __forceinline__ float2 upk2(unsigned long long v) {
    float2 f;
    asm("mov.b64 {%0, %1}, %2;" : "=f"(f.x), "=f"(f.y) : "l"(v));
    return f;
}
static __device__ __forceinline__ unsigned long long fma2(unsigned long long a,
                                                          unsigned long long b,
                                                          unsigned long long c) {
    unsigned long long d;
    asm("fma.rn.f32x2 %0, %1, %2, %3;" : "=l"(d) : "l"(a), "l"(b), "l"(c));
    return d;
}
static __device__ __forceinline__ unsigned long long mul2(unsigned long long a,
                                                          unsigned long long b) {
    unsigned long long d;
    asm("mul.rn.f32x2 %0, %1, %2;" : "=l"(d) : "l"(a), "l"(b));
    return d;
}
static __device__ __forceinline__ float lg2_approx(float x) {
    float y;
    asm("lg2.approx.f32 %0, %1;" : "=f"(y) : "f"(x));
    return y;
}

static __device__ __forceinline__ void pair_acc(float p0, float p1, float t0, float t1,
                                                unsigned long long dpair,
                                                unsigned long long ln2p,
                                                unsigned long long &acc) {
    const unsigned long long ONE2 = 0x3F8000003F800000ULL;   // {1,1}
    const unsigned long long NEG2 = 0xBF800000BF800000ULL;   // {-1,-1}
    const unsigned long long TWO2 = 0x4000000040000000ULL;   // {2,2}
    unsigned long long pp  = pk2(p0, p1);
    unsigned long long tt  = pk2(t0, t1);
    unsigned long long omp = fma2(pp, NEG2, ONE2);   // 1-p
    unsigned long long r   = fma2(pp, TWO2, NEG2);   // 2p-1
    unsigned long long x   = fma2(tt, r, omp);       // t?p:1-p
    unsigned long long q   = fma2(x,  NEG2, ONE2);   // 1-x
    unsigned long long a   = fma2(tt, dpair, ln2p);  // (t?alpha:1)*ln2
    unsigned long long m1  = mul2(q, q);
    unsigned long long m2  = mul2(m1, a);
    float2 xf = upk2(x);
    unsigned long long lg = pk2(lg2_approx(xf.x), lg2_approx(xf.y));  // 2x MUFU.LG2
    acc = fma2(lg, m2, acc);
}

__global__ void focal_zero_kernel() { g_sum = 0.0; }

__global__ void __launch_bounds__(256)
focal_main_kernel(const float* __restrict__ inp, const float* __restrict__ tgt,
                  const float* __restrict__ alpha, int n4) {
    int tid    = blockIdx.x * 256 + threadIdx.x;
    int stride = gridDim.x * 256;   // must be multiple of 16 (float4 groups per row)

    // Per-thread column group is invariant across grid-stride iterations.
    int colg = (tid & 15) * 4;
    float d0 = (alpha[colg + 0] - 1.0f) * LN2F;
    float d1 = (alpha[colg + 1] - 1.0f) * LN2F;
    float d2 = (alpha[colg + 2] - 1.0f) * LN2F;
    float d3 = (alpha[colg + 3] - 1.0f) * LN2F;
    unsigned long long dA = pk2(d0, d1);
    unsigned long long dB = pk2(d2, d3);
    unsigned long long ln2p = pk2(LN2F, LN2F);

    unsigned long long acc0 = 0ULL, acc1 = 0ULL;  // {0.0f, 0.0f}

    const float4* __restrict__ P4 = (const float4*)inp;
    const float4* __restrict__ T4 = (const float4*)tgt;

    for (int g = tid; g < n4; g += stride) {
        float4 p = P4[g];
        float4 t = T4[g];
        pair_acc(p.x, p.y, t.x, t.y, dA, ln2p, acc0);
        pair_acc(p.z, p.w, t.z, t.w, dB, ln2p, acc1);
    }

    float2 a0 = upk2(acc0);
    float2 a1 = upk2(acc1);
    float s = (a0.x + a0.y) + (a1.x + a1.y);

    // warp reduce
    #pragma unroll
    for (int o = 16; o > 0; o >>= 1) s += __shfl_xor_sync(0xffffffffu, s, o);

    __shared__ float ws[8];
    int w = threadIdx.x >> 5, l = threadIdx.x & 31;
    if (l == 0) ws[w] = s;
    __syncthreads();
    if (w == 0) {
        float v = (l < 8) ? ws[l] : 0.0f;
        #pragma unroll
        for (int o = 4; o > 0; o >>= 1) v += __shfl_xor_sync(0xffffffffu, v, o);
        if (l == 0) atomicAdd(&g_sum, (double)v);
    }
}

__global__ void focal_final_kernel(float* out, int n_total) {
    out[0] = (float)(-g_sum / (double)n_total);
}

extern "C" void kernel_launch(void* const* d_in, const int* in_sizes, int n_in,
                              void* d_out, int out_size) {
    const float* inp   = (const float*)d_in[0];
    const float* tgt   = (const float*)d_in[1];
    const float* alpha = (const float*)d_in[2];
    float* out = (float*)d_out;

    int n  = in_sizes[0];   // N*C = 16777216
    int n4 = n / 4;

    focal_zero_kernel<<<1, 1>>>();
    focal_main_kernel<<<1184, 256>>>(inp, tgt, alpha, n4);
    focal_final_kernel<<<1, 1>>>(out, n);
}